// round 9
// baseline (speedup 1.0000x reference)
#include <cuda_runtime.h>
#include <cstdint>

#define NN 8192
#define GGK 64
#define HH 128
#define LN_EPS 1e-5f

// ---------------- device scratch (no allocations allowed) ----------------
__device__ float g_x[NN * HH];      // node features
__device__ float g_y[NN * HH];      // tf32(dinv * x @ convW^T)
__device__ float g_t[NN * HH];      // conv output
__device__ float g_part[64 * NN];   // column-sum partials
__device__ float g_dinv[NN];

// ---------------- helpers ----------------
__device__ __forceinline__ uint32_t tf32r(float x) {
    uint32_t u;
    asm("cvt.rna.tf32.f32 %0, %1;" : "=r"(u) : "f"(x));
    return u;
}

__device__ __forceinline__ void mma_tf32(float c[4], const uint32_t a[4], const uint32_t b[2]) {
    asm volatile(
        "mma.sync.aligned.m16n8k8.row.col.f32.tf32.tf32.f32 "
        "{%0,%1,%2,%3}, {%4,%5,%6,%7}, {%8,%9}, {%0,%1,%2,%3};\n"
        : "+f"(c[0]), "+f"(c[1]), "+f"(c[2]), "+f"(c[3])
        : "r"(a[0]), "r"(a[1]), "r"(a[2]), "r"(a[3]), "r"(b[0]), "r"(b[1]));
}

__device__ __forceinline__ void cp_async16(void* sptr, const void* gptr) {
    uint32_t s = (uint32_t)__cvta_generic_to_shared(sptr);
    asm volatile("cp.async.cg.shared.global [%0], [%1], 16;\n" :: "r"(s), "l"(gptr));
}

// ---------------- kernel 1: column partial sums + adj copy ----------------
// grid (8, 64), 256 threads. Thread: 4 consecutive cols x 128 rows, float4.
__global__ void __launch_bounds__(256) deg_copy_kernel(const float* __restrict__ adj,
                                                       float* __restrict__ out_adj) {
    const int c4 = blockIdx.x * 256 + threadIdx.x;   // float4 column index
    const int r0 = blockIdx.y * 128;
    const size_t rs = NN / 4;
    const float4* src = (const float4*)adj + (size_t)r0 * rs + c4;
    float4* dst = (float4*)out_adj + (size_t)r0 * rs + c4;
    float s0 = 0.f, s1 = 0.f, s2 = 0.f, s3 = 0.f;
    #pragma unroll 4
    for (int r = 0; r < 128; r++) {
        float4 v = src[(size_t)r * rs];
        dst[(size_t)r * rs] = v;
        s0 += fmaxf(v.x, 0.f); s1 += fmaxf(v.y, 0.f);
        s2 += fmaxf(v.z, 0.f); s3 += fmaxf(v.w, 0.f);
    }
    float* p = g_part + (size_t)blockIdx.y * NN + c4 * 4;
    p[0] = s0; p[1] = s1; p[2] = s2; p[3] = s3;
}

// ---------------- kernel 2: dinv = rsqrt(colsum + 1) ----------------
__global__ void __launch_bounds__(256) dinv_kernel() {
    const int c = blockIdx.x * 256 + threadIdx.x;
    float s = 0.f;
    #pragma unroll 8
    for (int b = 0; b < 64; b++) s += g_part[(size_t)b * NN + c];
    g_dinv[c] = rsqrtf(s + 1.0f);   // self-loop weight 1 -> deg >= 1
}

// ---------------- small GEMM: OUT[n][h] = sum_g IN[n][g]*W[h][g] + epilogue ----
// MODE 0: + bias               (lin1)
// MODE 1: tf32(dinv[n] * acc)  (conv pre-pass producing Y)
// MODE 2: + bias -> LayerNorm -> ReLU (mlp block)
// CTA: 64 rows x 128 cols, 256 threads; thread = 8 rows x 4 cols.
template <int K, int MODE>
__global__ void __launch_bounds__(256) small_gemm(const float* __restrict__ IN,
                                                  const float* __restrict__ W,
                                                  const float* __restrict__ bias,
                                                  const float* __restrict__ lng,
                                                  const float* __restrict__ lnb,
                                                  float* __restrict__ OUT) {
    __shared__ float sXT[16][68];   // [g][n]
    __shared__ float sW[16][132];   // [g][h]
    const int t  = threadIdx.x;
    const int n0 = blockIdx.x * 64;
    const int hq = t & 31, nq = t >> 5;   // warp = all threads with same nq

    float acc[8][4];
    #pragma unroll
    for (int i = 0; i < 8; i++)
        #pragma unroll
        for (int j = 0; j < 4; j++) acc[i][j] = 0.f;

    for (int kc = 0; kc < K; kc += 16) {
        {   // IN tile [64 n][16 g] -> sXT[g][n]
            const int tn = t >> 2, tq = t & 3;
            float4 v = *(const float4*)(IN + (size_t)(n0 + tn) * K + kc + 4 * tq);
            sXT[4 * tq + 0][tn] = v.x; sXT[4 * tq + 1][tn] = v.y;
            sXT[4 * tq + 2][tn] = v.z; sXT[4 * tq + 3][tn] = v.w;
        }
        {   // W tile [128 h][16 g] -> sW[g][h]
            const int qq = t & 3, hh = t >> 2;
            #pragma unroll
            for (int rep = 0; rep < 2; rep++) {
                const int h = hh + rep * 64;
                float4 v = *(const float4*)(W + (size_t)h * K + kc + 4 * qq);
                sW[4 * qq + 0][h] = v.x; sW[4 * qq + 1][h] = v.y;
                sW[4 * qq + 2][h] = v.z; sW[4 * qq + 3][h] = v.w;
            }
        }
        __syncthreads();
        #pragma unroll
        for (int g = 0; g < 16; g++) {
            float4 xa = *(const float4*)&sXT[g][8 * nq];       // broadcast in warp
            float4 xb = *(const float4*)&sXT[g][8 * nq + 4];
            float4 wv = *(const float4*)&sW[g][4 * hq];
            float xs[8] = {xa.x, xa.y, xa.z, xa.w, xb.x, xb.y, xb.z, xb.w};
            float ws[4] = {wv.x, wv.y, wv.z, wv.w};
            #pragma unroll
            for (int i = 0; i < 8; i++)
                #pragma unroll
                for (int j = 0; j < 4; j++) acc[i][j] += xs[i] * ws[j];
        }
        __syncthreads();
    }

    if (MODE == 0) {
        float bv[4];
        #pragma unroll
        for (int j = 0; j < 4; j++) bv[j] = bias[4 * hq + j];
        #pragma unroll
        for (int i = 0; i < 8; i++) {
            const int n = n0 + 8 * nq + i;
            #pragma unroll
            for (int j = 0; j < 4; j++)
                OUT[(size_t)n * HH + 4 * hq + j] = acc[i][j] + bv[j];
        }
    } else if (MODE == 1) {
        #pragma unroll
        for (int i = 0; i < 8; i++) {
            const int n = n0 + 8 * nq + i;
            const float d = g_dinv[n];
            #pragma unroll
            for (int j = 0; j < 4; j++)
                OUT[(size_t)n * HH + 4 * hq + j] = __uint_as_float(tf32r(d * acc[i][j]));
        }
    } else {
        float bv[4], gv[4], lv[4];
        #pragma unroll
        for (int j = 0; j < 4; j++) {
            bv[j] = bias[4 * hq + j];
            gv[j] = lng[4 * hq + j];
            lv[j] = lnb[4 * hq + j];
        }
        #pragma unroll
        for (int i = 0; i < 8; i++) {
            float v[4];
            float s = 0.f, s2 = 0.f;
            #pragma unroll
            for (int j = 0; j < 4; j++) {
                v[j] = acc[i][j] + bv[j];
                s += v[j]; s2 += v[j] * v[j];
            }
            #pragma unroll
            for (int o = 16; o > 0; o >>= 1) {
                s  += __shfl_xor_sync(0xFFFFFFFFu, s, o);
                s2 += __shfl_xor_sync(0xFFFFFFFFu, s2, o);
            }
            const float mu  = s * (1.0f / HH);
            const float var = s2 * (1.0f / HH) - mu * mu;
            const float rstd = rsqrtf(var + LN_EPS);
            const int n = n0 + 8 * nq + i;
            #pragma unroll
            for (int j = 0; j < 4; j++)
                OUT[(size_t)n * HH + 4 * hq + j] =
                    fmaxf((v[j] - mu) * rstd * gv[j] + lv[j], 0.f);
        }
    }
}

// ---------------- big GEMM: out[c][h] = dinv[c]*(sum_r relu(adj[r][c])*Y[r][h] + Y[c][h]) + cb[h]
// 128 CTAs x 128 thr. CTA tile 64(c) x 128(h), BK=32, tf32 m16n8k8 mma,
// cp.async double-buffered. warps: 2(M) x 2(N), warp tile 32 x 64.
// smem: sA[2][32][72] raw adj tile (relu+tf32 at frag load), sB[2][32][136] Y tile.
#define SA_STRIDE 72
#define SB_STRIDE 136
#define SA_BUF (32 * SA_STRIDE)
#define SB_BUF (32 * SB_STRIDE)
#define SPMM_SMEM ((2 * SA_BUF + 2 * SB_BUF) * 4)

__device__ __forceinline__ void spmm_load(const float* __restrict__ adj,
                                          const float* __restrict__ Y,
                                          int c0, int it, int buf,
                                          float* sA, float* sB, int tid) {
    const float* ga = adj + (size_t)it * 32 * NN + c0;
    float* da = sA + buf * SA_BUF;
    #pragma unroll
    for (int i = 0; i < 4; i++) {          // 512 16B chunks, tile 32r x 64c
        const int j = tid + i * 128;
        const int r = j >> 4, cc = (j & 15) * 4;
        cp_async16(da + r * SA_STRIDE + cc, ga + (size_t)r * NN + cc);
    }
    const float* gb = Y + (size_t)it * 32 * HH;
    float* db = sB + buf * SB_BUF;
    #pragma unroll
    for (int i = 0; i < 8; i++) {          // 1024 16B chunks, tile 32r x 128h
        const int j = tid + i * 128;
        const int r = j >> 5, cc = (j & 31) * 4;
        cp_async16(db + r * SB_STRIDE + cc, gb + r * HH + cc);
    }
    asm volatile("cp.async.commit_group;\n" ::: "memory");
}

__global__ void __launch_bounds__(128) spmm_kernel(const float* __restrict__ adj,
                                                   const float* __restrict__ Y,
                                                   const float* __restrict__ cb,
                                                   float* __restrict__ OUT) {
    extern __shared__ float sm[];
    float* sA = sm;
    float* sB = sm + 2 * SA_BUF;
    const int tid  = threadIdx.x;
    const int lane = tid & 31, warp = tid >> 5;
    const int mw = warp & 1, nw = warp >> 1;
    const int gid = lane >> 2, tig = lane & 3;
    const int c0 = blockIdx.x * 64;

    float acc[2][8][4];
    #pragma unroll
    for (int mt = 0; mt < 2; mt++)
        #pragma unroll
        for (int nt = 0; nt < 8; nt++)
            #pragma unroll
            for (int j = 0; j < 4; j++) acc[mt][nt][j] = 0.f;

    spmm_load(adj, Y, c0, 0, 0, sA, sB, tid);

    for (int it = 0; it < NN / 32; it++) {
        const int buf = it & 1;
        if (it + 1 < NN / 32)
            spmm_load(adj, Y, c0, it + 1, buf ^ 1, sA, sB, tid);
        else
            asm volatile("cp.async.commit_group;\n" ::: "memory");
        asm volatile("cp.async.wait_group 1;\n" ::: "memory");
        __syncthreads();

        const float* a = sA + buf * SA_BUF;
        const float* b = sB + buf * SB_BUF;
        #pragma unroll
        for (int ks = 0; ks < 4; ks++) {
            const int kb = ks * 8;
            uint32_t af[2][4];
            #pragma unroll
            for (int mt = 0; mt < 2; mt++) {
                const int mb = mw * 32 + mt * 16 + gid;
                af[mt][0] = tf32r(fmaxf(a[(kb + tig) * SA_STRIDE + mb], 0.f));
                af[mt][1] = tf32r(fmaxf(a[(kb + tig) * SA_STRIDE + mb + 8], 0.f));
                af[mt][2] = tf32r(fmaxf(a[(kb + tig + 4) * SA_STRIDE + mb], 0.f));
                af[mt][3] = tf32r(fmaxf(a[(kb + tig + 4) * SA_STRIDE + mb + 8], 0.f));
            }
            #pragma unroll
            for (int nt = 0; nt < 8; nt++) {
                const int nb = nw * 64 + nt * 8 + gid;
                uint32_t bf[2];
                bf[0] = __float_as_uint(b[(kb + tig) * SB_STRIDE + nb]);
                bf[1] = __float_as_uint(b[(kb + tig + 4) * SB_STRIDE + nb]);
                mma_tf32(acc[0][nt], af[0], bf);
                mma_tf32(acc[1][nt], af[1], bf);
            }
        }
        __syncthreads();
    }

    // epilogue: self-loop (+Y[c]), dinv[c] scale, conv bias
    #pragma unroll
    for (int mt = 0; mt < 2; mt++) {
        const int r0 = c0 + mw * 32 + mt * 16 + gid;
        const int r1 = r0 + 8;
        const float d0 = g_dinv[r0], d1 = g_dinv[r1];
        #pragma unroll
        for (int nt = 0; nt < 8; nt++) {
            const int h = nw * 64 + nt * 8 + tig * 2;
            OUT[(size_t)r0 * HH + h]     = d0 * (acc[mt][nt][0] + Y[(size_t)r0 * HH + h])     + cb[h];
            OUT[(size_t)r0 * HH + h + 1] = d0 * (acc[mt][nt][1] + Y[(size_t)r0 * HH + h + 1]) + cb[h + 1];
            OUT[(size_t)r1 * HH + h]     = d1 * (acc[mt][nt][2] + Y[(size_t)r1 * HH + h])     + cb[h];
            OUT[(size_t)r1 * HH + h + 1] = d1 * (acc[mt][nt][3] + Y[(size_t)r1 * HH + h + 1]) + cb[h + 1];
        }
    }
}

// ---------------- launch ----------------
extern "C" void kernel_launch(void* const* d_in, const int* in_sizes, int n_in,
                              void* d_out, int out_size) {
    const float* X      = (const float*)d_in[0];
    const float* adj    = (const float*)d_in[1];
    const float* lin1_w = (const float*)d_in[2];
    const float* lin1_b = (const float*)d_in[3];
    const float* conv_w = (const float*)d_in[4];
    const float* conv_b = (const float*)d_in[5];
    const float* mlp_w  = (const float*)d_in[6];
    const float* mlp_b  = (const float*)d_in[7];
    const float* ln_g   = (const float*)d_in[8];
    const float* ln_b   = (const float*)d_in[9];

    float* out_z   = (float*)d_out;                     // [N, H]
    float* out_adj = (float*)d_out + (size_t)NN * HH;   // [N, N]

    float *gx = nullptr, *gy = nullptr, *gt = nullptr;
    cudaGetSymbolAddress((void**)&gx, g_x);
    cudaGetSymbolAddress((void**)&gy, g_y);
    cudaGetSymbolAddress((void**)&gt, g_t);

    cudaFuncSetAttribute(spmm_kernel,
                         cudaFuncAttributeMaxDynamicSharedMemorySize, SPMM_SMEM);

    // deg partials + adj copy to output
    deg_copy_kernel<<<dim3(8, 64), 256>>>(adj, out_adj);
    dinv_kernel<<<NN / 256, 256>>>();

    // x = X @ lin1_w^T + b
    small_gemm<GGK, 0><<<NN / 64, 256>>>(X, lin1_w, lin1_b, nullptr, nullptr, gx);

    for (int l = 0; l < 2; l++) {
        // Y = tf32(dinv * (x @ conv_w^T))
        small_gemm<HH, 1><<<NN / 64, 256>>>(gx, conv_w + (size_t)l * HH * HH,
                                            nullptr, nullptr, nullptr, gy);
        // t = dinv * (Ah^T @ Y) + conv_b
        spmm_kernel<<<NN / 64, 128, SPMM_SMEM>>>(adj, gy, conv_b + (size_t)l * HH, gt);
        // x = relu(LN(t @ mlp_w^T + mlp_b))
        small_gemm<HH, 2><<<NN / 64, 256>>>(gt, mlp_w + (size_t)l * HH * HH,
                                            mlp_b + (size_t)l * HH,
                                            ln_g + (size_t)l * HH,
                                            ln_b + (size_t)l * HH,
                                            (l == 1) ? out_z : gx);
    }
}